// round 2
// baseline (speedup 1.0000x reference)
#include <cuda_runtime.h>

// ---------------- geometry ----------------
#define GD0 27
#define GH0 127
#define GW0 127
#define NVOX (GD0*GH0*GW0)        // 435483
#define GD1 14
#define GH1 64
#define GW1 64
#define NC1 (GD1*GH1*GW1)         // 57344
#define GD2 7
#define GH2 32
#define GW2 32
#define NC2 (GD2*GH2*GW2)         // 7168
#define FS 64                     // fine buffer channel stride
#define CS 96                     // coarse buffer channel stride

// ---------------- static scratch (no allocations allowed) ----------------
__device__ float g_fineA[(size_t)NVOX * FS];   // ~111.5 MB
__device__ float g_fineB[(size_t)NVOX * FS];   // ~111.5 MB
__device__ float g_cA[NC1 * CS];
__device__ float g_cB[NC1 * CS];
__device__ float g_c2[NC2 * CS];
__device__ float g_mask[NC1];

// repacked weights: layout [tap][cout][cin]
__device__ float g_w0[27 * 32 * 3];
__device__ float g_w1[27 * 32 * 32];
__device__ float g_w2[27 * 64 * 32];
__device__ float g_w3[27 * 64 * 64];
__device__ float g_wd0[27 * 64 * 64];
__device__ float g_w4[27 * 96 * 64];
__device__ float g_w5[27 * 96 * 96];
__device__ float g_wd1[8 * 96 * 96];
__device__ float g_wi1[8 * 64 * 96];
__device__ float g_wi0[27 * 32 * 64];

// ---------------- helpers ----------------
// weights come in as (kz,ky,kx,ci,co) row-major; repack to [tap][co][ci]
__global__ void repack_kernel(const float* __restrict__ w, float* __restrict__ o,
                              int k3, int cin, int cout) {
    int i = blockIdx.x * blockDim.x + threadIdx.x;
    int tot = k3 * cin * cout;
    if (i >= tot) return;
    int co = i % cout;
    int r  = i / cout;
    int ci = r % cin;
    int t  = r / cin;
    o[(t * cout + co) * cin + ci] = w[i];
}

__global__ void scatter_kernel(const float* __restrict__ f, const int* __restrict__ coors,
                               float* __restrict__ X, int n) {
    int p = blockIdx.x * blockDim.x + threadIdx.x;
    if (p >= n) return;
    int z = coors[p * 4 + 1], y = coors[p * 4 + 2], x = coors[p * 4 + 3];
    size_t vox = (size_t)((z * GH0 + y) * GW0 + x) * FS;
    X[vox + 0] = f[p * 3 + 0];
    X[vox + 1] = f[p * 3 + 1];
    X[vox + 2] = f[p * 3 + 2];
}

// mask_m0: coarse voxel o active iff an active fine voxel lies in [2o-1, 2o+1]^3
__global__ void mask_kernel(const int* __restrict__ coors, float* __restrict__ mask, int n) {
    int p = blockIdx.x * blockDim.x + threadIdx.x;
    if (p >= n) return;
    int z = coors[p * 4 + 1], y = coors[p * 4 + 2], x = coors[p * 4 + 3];
    int zo[2], yo[2], xo[2];
    int nzc = 0, nyc = 0, nxc = 0;
    if ((z & 1) == 0) { zo[nzc++] = z >> 1; }
    else { zo[nzc++] = z >> 1; if ((z >> 1) + 1 < GD1) zo[nzc++] = (z >> 1) + 1; }
    if ((y & 1) == 0) { yo[nyc++] = y >> 1; }
    else { yo[nyc++] = y >> 1; if ((y >> 1) + 1 < GH1) yo[nyc++] = (y >> 1) + 1; }
    if ((x & 1) == 0) { xo[nxc++] = x >> 1; }
    else { xo[nxc++] = x >> 1; if ((x >> 1) + 1 < GW1) xo[nxc++] = (x >> 1) + 1; }
    for (int a = 0; a < nzc; a++)
        for (int b = 0; b < nyc; b++)
            for (int c = 0; c < nxc; c++)
                mask[(zo[a] * GH1 + yo[b]) * GW1 + xo[c]] = 1.0f;
}

template <int CIN>
__device__ __forceinline__ void dotrow4(const float* __restrict__ w,
                                        const float* __restrict__ xv, float4& a) {
    if constexpr ((CIN & 3) == 0) {
#pragma unroll
        for (int c = 0; c < CIN; c += 4) {
            float4 wv = *reinterpret_cast<const float4*>(w + c);
            float4 x4 = *reinterpret_cast<const float4*>(xv + c);
            a.x = fmaf(wv.x, x4.x, a.x);
            a.y = fmaf(wv.y, x4.y, a.y);
            a.z = fmaf(wv.z, x4.z, a.z);
            a.w = fmaf(wv.w, x4.w, a.w);
        }
    } else {
#pragma unroll
        for (int c = 0; c < CIN; c++) a.x = fmaf(w[c], xv[c], a.x);
    }
}

// ---------------- fine-level submanifold conv (k=3,s=1,p=1), outputs only at active points
template <int CIN, int COUT>
__global__ void __launch_bounds__(COUT) conv_fine_kernel(
    const float* __restrict__ X, float* __restrict__ Y,
    const int* __restrict__ coors, const float* __restrict__ Wt, int n) {
    __shared__ __align__(16) float xs[27 * CIN];
    int p = blockIdx.x;
    if (p >= n) return;
    int z = coors[p * 4 + 1], y = coors[p * 4 + 2], x = coors[p * 4 + 3];
    int t = threadIdx.x;
    for (int tap = 0; tap < 27; tap++) {
        int nz = z + tap / 9 - 1;
        int ny = y + (tap / 3) % 3 - 1;
        int nx = x + tap % 3 - 1;
        bool ok = (unsigned)nz < (unsigned)GD0 && (unsigned)ny < (unsigned)GH0 &&
                  (unsigned)nx < (unsigned)GW0;
        size_t base = ok ? (size_t)((nz * GH0 + ny) * GW0 + nx) * FS : 0;
        for (int c = t; c < CIN; c += COUT)
            xs[tap * CIN + c] = ok ? X[base + c] : 0.0f;
    }
    __syncthreads();
    float4 acc = make_float4(0.f, 0.f, 0.f, 0.f);
    for (int tap = 0; tap < 27; tap++)
        dotrow4<CIN>(Wt + (tap * COUT + t) * CIN, xs + tap * CIN, acc);
    size_t vox = (size_t)((z * GH0 + y) * GW0 + x) * FS;
    Y[vox + t] = acc.x + acc.y + acc.z + acc.w;
}

// ---------------- down0: k=3, s=2, p=1, fine -> coarse, dense output
__global__ void __launch_bounds__(64) conv_down0_kernel(
    const float* __restrict__ X, float* __restrict__ Y, const float* __restrict__ Wt) {
    constexpr int CIN = 64, COUT = 64;
    __shared__ __align__(16) float xs[27 * CIN];
    int o = blockIdx.x;
    int oz = o >> 12, oy = (o >> 6) & 63, ox = o & 63;
    int t = threadIdx.x;
    for (int tap = 0; tap < 27; tap++) {
        int fz = 2 * oz + tap / 9 - 1;
        int fy = 2 * oy + (tap / 3) % 3 - 1;
        int fx = 2 * ox + tap % 3 - 1;
        bool ok = (unsigned)fz < (unsigned)GD0 && (unsigned)fy < (unsigned)GH0 &&
                  (unsigned)fx < (unsigned)GW0;
        size_t base = ok ? (size_t)((fz * GH0 + fy) * GW0 + fx) * FS : 0;
        xs[tap * CIN + t] = ok ? X[base + t] : 0.0f;
    }
    __syncthreads();
    float4 acc = make_float4(0.f, 0.f, 0.f, 0.f);
    for (int tap = 0; tap < 27; tap++)
        dotrow4<CIN>(Wt + (tap * COUT + t) * CIN, xs + tap * CIN, acc);
    Y[o * CS + t] = acc.x + acc.y + acc.z + acc.w;
}

// ---------------- coarse submanifold conv (k=3,s=1,p=1), dense, output *= mask
template <int CIN, int COUT>
__global__ void __launch_bounds__(COUT) conv_coarse_kernel(
    const float* __restrict__ X, float* __restrict__ Y,
    const float* __restrict__ Wt, const float* __restrict__ mask) {
    __shared__ __align__(16) float xs[27 * CIN];
    int o = blockIdx.x;
    int t = threadIdx.x;
    float mv = mask[o];
    if (mv == 0.0f) { Y[o * CS + t] = 0.0f; return; }
    int oz = o >> 12, oy = (o >> 6) & 63, ox = o & 63;
    for (int tap = 0; tap < 27; tap++) {
        int nz = oz + tap / 9 - 1;
        int ny = oy + (tap / 3) % 3 - 1;
        int nx = ox + tap % 3 - 1;
        bool ok = (unsigned)nz < (unsigned)GD1 && (unsigned)ny < (unsigned)GH1 &&
                  (unsigned)nx < (unsigned)GW1;
        size_t base = ok ? (size_t)((nz * GH1 + ny) * GW1 + nx) * CS : 0;
        for (int c = t; c < CIN; c += COUT)
            xs[tap * CIN + c] = ok ? X[base + c] : 0.0f;
    }
    __syncthreads();
    float4 acc = make_float4(0.f, 0.f, 0.f, 0.f);
    for (int tap = 0; tap < 27; tap++)
        dotrow4<CIN>(Wt + (tap * COUT + t) * CIN, xs + tap * CIN, acc);
    Y[o * CS + t] = (acc.x + acc.y + acc.z + acc.w) * mv;
}

// ---------------- down1: k=2, s=2, p=0, coarse -> coarse2, dense
__global__ void __launch_bounds__(96) conv_down1_kernel(
    const float* __restrict__ X, float* __restrict__ Y, const float* __restrict__ Wt) {
    constexpr int CIN = 96, COUT = 96;
    __shared__ __align__(16) float xs[8 * CIN];
    int o = blockIdx.x;
    int oz = o / (GH2 * GW2), oy = (o / GW2) % GH2, ox = o % GW2;
    int t = threadIdx.x;
    for (int tap = 0; tap < 8; tap++) {
        int nz = 2 * oz + (tap >> 2);
        int ny = 2 * oy + ((tap >> 1) & 1);
        int nx = 2 * ox + (tap & 1);
        size_t base = (size_t)((nz * GH1 + ny) * GW1 + nx) * CS;
        xs[tap * CIN + t] = X[base + t];
    }
    __syncthreads();
    float4 acc = make_float4(0.f, 0.f, 0.f, 0.f);
    for (int tap = 0; tap < 8; tap++)
        dotrow4<CIN>(Wt + (tap * COUT + t) * CIN, xs + tap * CIN, acc);
    Y[o * CS + t] = acc.x + acc.y + acc.z + acc.w;
}

// ---------------- inv1: transposed k=2,s=2,p=0 : exactly one tap per output
__global__ void __launch_bounds__(64) inv1_kernel(
    const float* __restrict__ X2, float* __restrict__ Y,
    const float* __restrict__ Wt, const float* __restrict__ mask) {
    constexpr int CIN = 96, COUT = 64;
    __shared__ __align__(16) float xs[CIN];
    int o = blockIdx.x;
    int t = threadIdx.x;
    float mv = mask[o];
    if (mv == 0.0f) { Y[o * CS + t] = 0.0f; return; }
    int oz = o >> 12, oy = (o >> 6) & 63, ox = o & 63;
    int m = (((oz >> 1) * GH2) + (oy >> 1)) * GW2 + (ox >> 1);
    int tap = ((oz & 1) * 2 + (oy & 1)) * 2 + (ox & 1);
    for (int c = t; c < CIN; c += COUT) xs[c] = X2[(size_t)m * CS + c];
    __syncthreads();
    float4 acc = make_float4(0.f, 0.f, 0.f, 0.f);
    dotrow4<CIN>(Wt + (tap * COUT + t) * CIN, xs, acc);
    Y[o * CS + t] = (acc.x + acc.y + acc.z + acc.w) * mv;
}

// ---------------- inv0: transposed k=3,s=2,p=1 : 1-2 taps per dim, output gathered to points
__global__ void __launch_bounds__(32) inv0_kernel(
    const float* __restrict__ X, float* __restrict__ out,
    const int* __restrict__ coors, const float* __restrict__ Wt, int n) {
    constexpr int CIN = 64, COUT = 32;
    __shared__ __align__(16) float xs[CIN];
    int p = blockIdx.x;
    if (p >= n) return;
    int z = coors[p * 4 + 1], y = coors[p * 4 + 2], x = coors[p * 4 + 3];
    int t = threadIdx.x;

    int mzv[2], wzv[2], myv[2], wyv[2], mxv[2], wxv[2];
    int nzc = 0, nyc = 0, nxc = 0;
    if ((z & 1) == 0) { mzv[0] = z >> 1; wzv[0] = 1; nzc = 1; }
    else {
        mzv[nzc] = z >> 1; wzv[nzc] = 2; nzc++;
        if ((z >> 1) + 1 < GD1) { mzv[nzc] = (z >> 1) + 1; wzv[nzc] = 0; nzc++; }
    }
    if ((y & 1) == 0) { myv[0] = y >> 1; wyv[0] = 1; nyc = 1; }
    else {
        myv[nyc] = y >> 1; wyv[nyc] = 2; nyc++;
        if ((y >> 1) + 1 < GH1) { myv[nyc] = (y >> 1) + 1; wyv[nyc] = 0; nyc++; }
    }
    if ((x & 1) == 0) { mxv[0] = x >> 1; wxv[0] = 1; nxc = 1; }
    else {
        mxv[nxc] = x >> 1; wxv[nxc] = 2; nxc++;
        if ((x >> 1) + 1 < GW1) { mxv[nxc] = (x >> 1) + 1; wxv[nxc] = 0; nxc++; }
    }

    float4 acc = make_float4(0.f, 0.f, 0.f, 0.f);
    for (int a = 0; a < nzc; a++)
        for (int b = 0; b < nyc; b++)
            for (int c = 0; c < nxc; c++) {
                int m = ((mzv[a] * GH1) + myv[b]) * GW1 + mxv[c];
                int tap = (wzv[a] * 3 + wyv[b]) * 3 + wxv[c];
                xs[t] = X[(size_t)m * CS + t];
                xs[t + 32] = X[(size_t)m * CS + t + 32];
                __syncthreads();
                dotrow4<CIN>(Wt + (tap * COUT + t) * CIN, xs, acc);
                __syncthreads();
            }
    out[(size_t)p * COUT + t] = acc.x + acc.y + acc.z + acc.w;
}

// ---------------- launch ----------------
extern "C" void kernel_launch(void* const* d_in, const int* in_sizes, int n_in,
                              void* d_out, int out_size) {
    const float* features = (const float*)d_in[0];
    const int* coors      = (const int*)d_in[1];
    // weights are the LAST 10 inputs (robust to whether batch_size is passed)
    int wb = n_in - 10;
    const float* w_sub0  = (const float*)d_in[wb + 0];
    const float* w_sub1  = (const float*)d_in[wb + 1];
    const float* w_sub2  = (const float*)d_in[wb + 2];
    const float* w_sub3  = (const float*)d_in[wb + 3];
    const float* w_down0 = (const float*)d_in[wb + 4];
    const float* w_sub4  = (const float*)d_in[wb + 5];
    const float* w_sub5  = (const float*)d_in[wb + 6];
    const float* w_down1 = (const float*)d_in[wb + 7];
    const float* w_inv1  = (const float*)d_in[wb + 8];
    const float* w_inv0  = (const float*)d_in[wb + 9];

    int n = in_sizes[0] / 3;

    float *fA, *fB, *cA, *cB, *c2p, *maskp;
    float *pw0, *pw1, *pw2, *pw3, *pwd0, *pw4, *pw5, *pwd1, *pwi1, *pwi0;
    cudaGetSymbolAddress((void**)&fA, g_fineA);
    cudaGetSymbolAddress((void**)&fB, g_fineB);
    cudaGetSymbolAddress((void**)&cA, g_cA);
    cudaGetSymbolAddress((void**)&cB, g_cB);
    cudaGetSymbolAddress((void**)&c2p, g_c2);
    cudaGetSymbolAddress((void**)&maskp, g_mask);
    cudaGetSymbolAddress((void**)&pw0, g_w0);
    cudaGetSymbolAddress((void**)&pw1, g_w1);
    cudaGetSymbolAddress((void**)&pw2, g_w2);
    cudaGetSymbolAddress((void**)&pw3, g_w3);
    cudaGetSymbolAddress((void**)&pwd0, g_wd0);
    cudaGetSymbolAddress((void**)&pw4, g_w4);
    cudaGetSymbolAddress((void**)&pw5, g_w5);
    cudaGetSymbolAddress((void**)&pwd1, g_wd1);
    cudaGetSymbolAddress((void**)&pwi1, g_wi1);
    cudaGetSymbolAddress((void**)&pwi0, g_wi0);

    auto rp = [](const float* src, float* dst, int k3, int cin, int cout) {
        int tot = k3 * cin * cout;
        repack_kernel<<<(tot + 255) / 256, 256>>>(src, dst, k3, cin, cout);
    };
    rp(w_sub0, pw0, 27, 3, 32);
    rp(w_sub1, pw1, 27, 32, 32);
    rp(w_sub2, pw2, 27, 32, 64);
    rp(w_sub3, pw3, 27, 64, 64);
    rp(w_down0, pwd0, 27, 64, 64);
    rp(w_sub4, pw4, 27, 64, 96);
    rp(w_sub5, pw5, 27, 96, 96);
    rp(w_down1, pwd1, 8, 96, 96);
    rp(w_inv1, pwi1, 8, 96, 64);
    rp(w_inv0, pwi0, 27, 64, 32);

    cudaMemsetAsync(fA, 0, (size_t)NVOX * FS * sizeof(float), 0);
    cudaMemsetAsync(fB, 0, (size_t)NVOX * FS * sizeof(float), 0);
    cudaMemsetAsync(maskp, 0, NC1 * sizeof(float), 0);

    scatter_kernel<<<(n + 255) / 256, 256>>>(features, coors, fA, n);
    mask_kernel<<<(n + 255) / 256, 256>>>(coors, maskp, n);

    conv_fine_kernel<3, 32><<<n, 32>>>(fA, fB, coors, pw0, n);
    conv_fine_kernel<32, 32><<<n, 32>>>(fB, fA, coors, pw1, n);
    conv_fine_kernel<32, 64><<<n, 64>>>(fA, fB, coors, pw2, n);
    conv_fine_kernel<64, 64><<<n, 64>>>(fB, fA, coors, pw3, n);

    conv_down0_kernel<<<NC1, 64>>>(fA, cA, pwd0);
    conv_coarse_kernel<64, 96><<<NC1, 96>>>(cA, cB, pw4, maskp);
    conv_coarse_kernel<96, 96><<<NC1, 96>>>(cB, cA, pw5, maskp);
    conv_down1_kernel<<<NC2, 96>>>(cA, c2p, pwd1);
    inv1_kernel<<<NC1, 64>>>(c2p, cB, pwi1, maskp);
    inv0_kernel<<<n, 32>>>(cB, (float*)d_out, coors, pwi0, n);
}

// round 3
// speedup vs baseline: 11.5044x; 11.5044x over previous
#include <cuda_runtime.h>

// ---------------- geometry ----------------
#define GD0 27
#define GH0 127
#define GW0 127
#define NVOX (GD0*GH0*GW0)        // 435483
#define GD1 14
#define GH1 64
#define GW1 64
#define NC1 (GD1*GH1*GW1)         // 57344
#define GD2 7
#define GH2 32
#define GW2 32
#define NC2 (GD2*GH2*GW2)         // 7168
#define FS 64                     // fine buffer channel stride
#define CS 96                     // coarse buffer channel stride

// ---------------- static scratch ----------------
__device__ float g_fineA[(size_t)NVOX * FS];   // ~111.5 MB
__device__ float g_fineB[(size_t)NVOX * FS];   // ~111.5 MB
__device__ float g_cA[NC1 * CS];
__device__ float g_cB[NC1 * CS];
__device__ float g_c2[NC2 * CS];
__device__ float g_mask[NC1];
// repacked weights [tap][cout][cin] (only small layers need this layout)
__device__ float g_wi1[8 * 64 * 96];
__device__ float g_wi0[27 * 32 * 64];

// ---------------- small helpers ----------------
__global__ void repack_kernel(const float* __restrict__ w, float* __restrict__ o,
                              int k3, int cin, int cout) {
    int i = blockIdx.x * blockDim.x + threadIdx.x;
    int tot = k3 * cin * cout;
    if (i >= tot) return;
    int co = i % cout;
    int r  = i / cout;
    int ci = r % cin;
    int t  = r / cin;
    o[(t * cout + co) * cin + ci] = w[i];
}

__global__ void scatter_kernel(const float* __restrict__ f, const int* __restrict__ coors,
                               float* __restrict__ X, int n) {
    int p = blockIdx.x * blockDim.x + threadIdx.x;
    if (p >= n) return;
    int z = coors[p * 4 + 1], y = coors[p * 4 + 2], x = coors[p * 4 + 3];
    size_t vox = (size_t)((z * GH0 + y) * GW0 + x) * FS;
    X[vox + 0] = f[p * 3 + 0];
    X[vox + 1] = f[p * 3 + 1];
    X[vox + 2] = f[p * 3 + 2];
}

__global__ void mask_kernel(const int* __restrict__ coors, float* __restrict__ mask, int n) {
    int p = blockIdx.x * blockDim.x + threadIdx.x;
    if (p >= n) return;
    int z = coors[p * 4 + 1], y = coors[p * 4 + 2], x = coors[p * 4 + 3];
    int zo[2], yo[2], xo[2];
    int nzc = 0, nyc = 0, nxc = 0;
    if ((z & 1) == 0) { zo[nzc++] = z >> 1; }
    else { zo[nzc++] = z >> 1; if ((z >> 1) + 1 < GD1) zo[nzc++] = (z >> 1) + 1; }
    if ((y & 1) == 0) { yo[nyc++] = y >> 1; }
    else { yo[nyc++] = y >> 1; if ((y >> 1) + 1 < GH1) yo[nyc++] = (y >> 1) + 1; }
    if ((x & 1) == 0) { xo[nxc++] = x >> 1; }
    else { xo[nxc++] = x >> 1; if ((x >> 1) + 1 < GW1) xo[nxc++] = (x >> 1) + 1; }
    for (int a = 0; a < nzc; a++)
        for (int b = 0; b < nyc; b++)
            for (int c = 0; c < nxc; c++)
                mask[(zo[a] * GH1 + yo[b]) * GW1 + xo[c]] = 1.0f;
}

__device__ __forceinline__ void fma4(float4& a, float4 w, float x) {
    a.x = fmaf(w.x, x, a.x);
    a.y = fmaf(w.y, x, a.y);
    a.z = fmaf(w.z, x, a.z);
    a.w = fmaf(w.w, x, a.w);
}

template <int CIN>
__device__ __forceinline__ void dotrow4(const float* __restrict__ w,
                                        const float* __restrict__ xv, float4& a) {
#pragma unroll
    for (int c = 0; c < CIN; c += 4) {
        float4 wv = *reinterpret_cast<const float4*>(w + c);
        float4 x4 = *reinterpret_cast<const float4*>(xv + c);
        a.x = fmaf(wv.x, x4.x, a.x);
        a.y = fmaf(wv.y, x4.y, a.y);
        a.z = fmaf(wv.z, x4.z, a.z);
        a.w = fmaf(wv.w, x4.w, a.w);
    }
}

// ---------------- sub0: 3->32, per-point (tiny), direct weight layout [tap][ci][co]
__global__ void __launch_bounds__(32) conv_sub0_kernel(
    const float* __restrict__ X, float* __restrict__ Y,
    const int* __restrict__ coors, const float* __restrict__ W, int n) {
    __shared__ float xs[81];
    int p = blockIdx.x;
    if (p >= n) return;
    int z = coors[p * 4 + 1], y = coors[p * 4 + 2], x = coors[p * 4 + 3];
    int t = threadIdx.x;
    for (int i = t; i < 81; i += 32) {
        int tap = i / 3, ci = i % 3;
        int nz = z + tap / 9 - 1;
        int ny = y + (tap / 3) % 3 - 1;
        int nx = x + tap % 3 - 1;
        bool ok = (unsigned)nz < (unsigned)GD0 && (unsigned)ny < (unsigned)GH0 &&
                  (unsigned)nx < (unsigned)GW0;
        xs[i] = ok ? X[(size_t)((nz * GH0 + ny) * GW0 + nx) * FS + ci] : 0.0f;
    }
    __syncthreads();
    float a = 0.f;
#pragma unroll
    for (int i = 0; i < 81; i++) a = fmaf(W[i * 32 + t], xs[i], a);
    size_t v = (size_t)((z * GH0 + y) * GW0 + x) * FS;
    Y[v + t] = a;
}

// ---------------- fine submanifold conv, tiled: M=TM*8 points, all Cout, per block
// weights in ORIGINAL layout [tap][ci][co] (no repack needed)
template <int CIN, int COUT, int TM>
__global__ void __launch_bounds__((COUT / 4) * TM) conv_fine_tiled(
    const float* __restrict__ X, float* __restrict__ Y,
    const int* __restrict__ coors, const float* __restrict__ Wt, int n) {
    constexpr int TC = COUT / 4;
    constexpr int THREADS = TC * TM;
    constexpr int MT = TM * 8;
    constexpr int XPAD = MT + 4;
    __shared__ __align__(16) float xs[CIN * XPAD];
    __shared__ int s_z[MT], s_y[MT], s_x[MT];
    int t = threadIdx.x;
    int p0 = blockIdx.x * MT;
    for (int i = t; i < MT; i += THREADS) {
        int p = p0 + i;
        int zz = -4, yy = 0, xv = 0;
        if (p < n) { zz = coors[p * 4 + 1]; yy = coors[p * 4 + 2]; xv = coors[p * 4 + 3]; }
        s_z[i] = zz; s_y[i] = yy; s_x[i] = xv;
    }
    float4 acc[8];
#pragma unroll
    for (int j = 0; j < 8; j++) acc[j] = make_float4(0.f, 0.f, 0.f, 0.f);
    int tc = t % TC, tm = t / TC;

    for (int tap = 0; tap < 27; tap++) {
        int dz = tap / 9 - 1, dy = (tap / 3) % 3 - 1, dx = tap % 3 - 1;
        __syncthreads();
        for (int i = t; i < MT * CIN; i += THREADS) {
            int m = i / CIN, ci = i - m * CIN;
            int nz = s_z[m] + dz, ny = s_y[m] + dy, nx = s_x[m] + dx;
            bool ok = (unsigned)nz < (unsigned)GD0 && (unsigned)ny < (unsigned)GH0 &&
                      (unsigned)nx < (unsigned)GW0;
            xs[ci * XPAD + m] = ok ? X[(size_t)((nz * GH0 + ny) * GW0 + nx) * FS + ci] : 0.0f;
        }
        __syncthreads();
        const float* wp = Wt + tap * CIN * COUT + tc * 4;
#pragma unroll 8
        for (int ci = 0; ci < CIN; ci++) {
            float4 w4 = *reinterpret_cast<const float4*>(wp + ci * COUT);
            float4 xa = *reinterpret_cast<const float4*>(xs + ci * XPAD + tm * 8);
            float4 xb = *reinterpret_cast<const float4*>(xs + ci * XPAD + tm * 8 + 4);
            fma4(acc[0], w4, xa.x); fma4(acc[1], w4, xa.y);
            fma4(acc[2], w4, xa.z); fma4(acc[3], w4, xa.w);
            fma4(acc[4], w4, xb.x); fma4(acc[5], w4, xb.y);
            fma4(acc[6], w4, xb.z); fma4(acc[7], w4, xb.w);
        }
    }
#pragma unroll
    for (int j = 0; j < 8; j++) {
        int m = tm * 8 + j;
        int p = p0 + m;
        if (p < n) {
            size_t v = (size_t)((s_z[m] * GH0 + s_y[m]) * GW0 + s_x[m]) * FS;
            *reinterpret_cast<float4*>(&Y[v + tc * 4]) = acc[j];
        }
    }
}

// ---------------- grid (dense) tiled conv: MODE 0=coarse subm(mask), 1=down0(fine->coarse s2), 2=down1(k2 s2)
template <int CIN, int COUT, int TM, int XSTR, int NTAPS, int MODE>
__global__ void __launch_bounds__((COUT / 4) * TM) conv_grid_tiled(
    const float* __restrict__ X, float* __restrict__ Y,
    const float* __restrict__ Wt, const float* __restrict__ mask) {
    constexpr int TC = COUT / 4;
    constexpr int THREADS = TC * TM;
    constexpr int MT = TM * 8;
    constexpr int XPAD = MT + 4;
    __shared__ __align__(16) float xs[CIN * XPAD];
    __shared__ float s_mk[MT];
    int t = threadIdx.x;
    int o0 = blockIdx.x * MT;
    if (MODE == 0) {
        for (int i = t; i < MT; i += THREADS) s_mk[i] = mask[o0 + i];
    }
    float4 acc[8];
#pragma unroll
    for (int j = 0; j < 8; j++) acc[j] = make_float4(0.f, 0.f, 0.f, 0.f);
    int tc = t % TC, tm = t / TC;

    for (int tap = 0; tap < NTAPS; tap++) {
        int dz, dy, dx;
        if (NTAPS == 27) { dz = tap / 9 - 1; dy = (tap / 3) % 3 - 1; dx = tap % 3 - 1; }
        else             { dz = tap >> 2;    dy = (tap >> 1) & 1;    dx = tap & 1; }
        __syncthreads();
        for (int i = t; i < MT * CIN; i += THREADS) {
            int m = i / CIN, ci = i - m * CIN;
            int o = o0 + m;
            int oz, oy, ox;
            if (MODE == 2) { oz = o >> 10; oy = (o >> 5) & 31; ox = o & 31; }
            else           { oz = o >> 12; oy = (o >> 6) & 63; ox = o & 63; }
            int nz, ny, nx;
            bool ok;
            size_t base;
            if (MODE == 0) {
                nz = oz + dz; ny = oy + dy; nx = ox + dx;
                ok = (unsigned)nz < (unsigned)GD1 && (unsigned)ny < (unsigned)GH1 &&
                     (unsigned)nx < (unsigned)GW1;
                base = (size_t)((nz * GH1 + ny) * GW1 + nx) * XSTR;
            } else if (MODE == 1) {
                nz = 2 * oz + dz; ny = 2 * oy + dy; nx = 2 * ox + dx;
                ok = (unsigned)nz < (unsigned)GD0 && (unsigned)ny < (unsigned)GH0 &&
                     (unsigned)nx < (unsigned)GW0;
                base = (size_t)((nz * GH0 + ny) * GW0 + nx) * XSTR;
            } else {
                nz = 2 * oz + dz; ny = 2 * oy + dy; nx = 2 * ox + dx;
                ok = true;
                base = (size_t)((nz * GH1 + ny) * GW1 + nx) * XSTR;
            }
            xs[ci * XPAD + m] = ok ? X[base + ci] : 0.0f;
        }
        __syncthreads();
        const float* wp = Wt + tap * CIN * COUT + tc * 4;
#pragma unroll 8
        for (int ci = 0; ci < CIN; ci++) {
            float4 w4 = *reinterpret_cast<const float4*>(wp + ci * COUT);
            float4 xa = *reinterpret_cast<const float4*>(xs + ci * XPAD + tm * 8);
            float4 xb = *reinterpret_cast<const float4*>(xs + ci * XPAD + tm * 8 + 4);
            fma4(acc[0], w4, xa.x); fma4(acc[1], w4, xa.y);
            fma4(acc[2], w4, xa.z); fma4(acc[3], w4, xa.w);
            fma4(acc[4], w4, xb.x); fma4(acc[5], w4, xb.y);
            fma4(acc[6], w4, xb.z); fma4(acc[7], w4, xb.w);
        }
    }
#pragma unroll
    for (int j = 0; j < 8; j++) {
        int m = tm * 8 + j;
        int o = o0 + m;
        float4 r = acc[j];
        if (MODE == 0) {
            float mv = s_mk[m];
            r.x *= mv; r.y *= mv; r.z *= mv; r.w *= mv;
        }
        *reinterpret_cast<float4*>(&Y[(size_t)o * CS + tc * 4]) = r;
    }
}

// ---------------- inv1: transposed k=2,s=2,p=0 : one tap per output (repacked weights)
__global__ void __launch_bounds__(64) inv1_kernel(
    const float* __restrict__ X2, float* __restrict__ Y,
    const float* __restrict__ Wt, const float* __restrict__ mask) {
    constexpr int CIN = 96;
    __shared__ __align__(16) float xs[CIN];
    int o = blockIdx.x;
    int t = threadIdx.x;
    float mv = mask[o];
    if (mv == 0.0f) { Y[o * CS + t] = 0.0f; return; }
    int oz = o >> 12, oy = (o >> 6) & 63, ox = o & 63;
    int m = (((oz >> 1) * GH2) + (oy >> 1)) * GW2 + (ox >> 1);
    int tap = ((oz & 1) * 2 + (oy & 1)) * 2 + (ox & 1);
    for (int c = t; c < CIN; c += 64) xs[c] = X2[(size_t)m * CS + c];
    __syncthreads();
    float4 acc = make_float4(0.f, 0.f, 0.f, 0.f);
    dotrow4<CIN>(Wt + (tap * 64 + t) * CIN, xs, acc);
    Y[o * CS + t] = (acc.x + acc.y + acc.z + acc.w) * mv;
}

// ---------------- inv0: transposed k=3,s=2,p=1, gathered to points (repacked weights)
__global__ void __launch_bounds__(32) inv0_kernel(
    const float* __restrict__ X, float* __restrict__ out,
    const int* __restrict__ coors, const float* __restrict__ Wt, int n) {
    constexpr int CIN = 64, COUT = 32;
    __shared__ __align__(16) float xs[CIN];
    int p = blockIdx.x;
    if (p >= n) return;
    int z = coors[p * 4 + 1], y = coors[p * 4 + 2], x = coors[p * 4 + 3];
    int t = threadIdx.x;

    int mzv[2], wzv[2], myv[2], wyv[2], mxv[2], wxv[2];
    int nzc = 0, nyc = 0, nxc = 0;
    if ((z & 1) == 0) { mzv[0] = z >> 1; wzv[0] = 1; nzc = 1; }
    else {
        mzv[nzc] = z >> 1; wzv[nzc] = 2; nzc++;
        if ((z >> 1) + 1 < GD1) { mzv[nzc] = (z >> 1) + 1; wzv[nzc] = 0; nzc++; }
    }
    if ((y & 1) == 0) { myv[0] = y >> 1; wyv[0] = 1; nyc = 1; }
    else {
        myv[nyc] = y >> 1; wyv[nyc] = 2; nyc++;
        if ((y >> 1) + 1 < GH1) { myv[nyc] = (y >> 1) + 1; wyv[nyc] = 0; nyc++; }
    }
    if ((x & 1) == 0) { mxv[0] = x >> 1; wxv[0] = 1; nxc = 1; }
    else {
        mxv[nxc] = x >> 1; wxv[nxc] = 2; nxc++;
        if ((x >> 1) + 1 < GW1) { mxv[nxc] = (x >> 1) + 1; wxv[nxc] = 0; nxc++; }
    }

    float4 acc = make_float4(0.f, 0.f, 0.f, 0.f);
    for (int a = 0; a < nzc; a++)
        for (int b = 0; b < nyc; b++)
            for (int c = 0; c < nxc; c++) {
                int m = ((mzv[a] * GH1) + myv[b]) * GW1 + mxv[c];
                int tap = (wzv[a] * 3 + wyv[b]) * 3 + wxv[c];
                xs[t] = X[(size_t)m * CS + t];
                xs[t + 32] = X[(size_t)m * CS + t + 32];
                __syncthreads();
                dotrow4<CIN>(Wt + (tap * COUT + t) * CIN, xs, acc);
                __syncthreads();
            }
    out[(size_t)p * COUT + t] = acc.x + acc.y + acc.z + acc.w;
}

// ---------------- launch ----------------
extern "C" void kernel_launch(void* const* d_in, const int* in_sizes, int n_in,
                              void* d_out, int out_size) {
    const float* features = (const float*)d_in[0];
    const int* coors      = (const int*)d_in[1];
    int wb = n_in - 10;
    const float* w_sub0  = (const float*)d_in[wb + 0];
    const float* w_sub1  = (const float*)d_in[wb + 1];
    const float* w_sub2  = (const float*)d_in[wb + 2];
    const float* w_sub3  = (const float*)d_in[wb + 3];
    const float* w_down0 = (const float*)d_in[wb + 4];
    const float* w_sub4  = (const float*)d_in[wb + 5];
    const float* w_sub5  = (const float*)d_in[wb + 6];
    const float* w_down1 = (const float*)d_in[wb + 7];
    const float* w_inv1  = (const float*)d_in[wb + 8];
    const float* w_inv0  = (const float*)d_in[wb + 9];

    int n = in_sizes[0] / 3;

    float *fA, *fB, *cA, *cB, *c2p, *maskp, *pwi1, *pwi0;
    cudaGetSymbolAddress((void**)&fA, g_fineA);
    cudaGetSymbolAddress((void**)&fB, g_fineB);
    cudaGetSymbolAddress((void**)&cA, g_cA);
    cudaGetSymbolAddress((void**)&cB, g_cB);
    cudaGetSymbolAddress((void**)&c2p, g_c2);
    cudaGetSymbolAddress((void**)&maskp, g_mask);
    cudaGetSymbolAddress((void**)&pwi1, g_wi1);
    cudaGetSymbolAddress((void**)&pwi0, g_wi0);

    // repack only the two small transposed-layout consumers
    repack_kernel<<<(8 * 96 * 64 + 255) / 256, 256>>>(w_inv1, pwi1, 8, 96, 64);
    repack_kernel<<<(27 * 64 * 32 + 255) / 256, 256>>>(w_inv0, pwi0, 27, 64, 32);

    cudaMemsetAsync(fA, 0, (size_t)NVOX * FS * sizeof(float), 0);
    cudaMemsetAsync(fB, 0, (size_t)NVOX * FS * sizeof(float), 0);
    cudaMemsetAsync(maskp, 0, NC1 * sizeof(float), 0);

    scatter_kernel<<<(n + 255) / 256, 256>>>(features, coors, fA, n);
    mask_kernel<<<(n + 255) / 256, 256>>>(coors, maskp, n);

    // fine level (submanifold, active points only)
    conv_sub0_kernel<<<n, 32>>>(fA, fB, coors, w_sub0, n);
    conv_fine_tiled<32, 32, 16><<<(n + 127) / 128, 128>>>(fB, fA, coors, w_sub1, n);
    conv_fine_tiled<32, 64, 8><<<(n + 63) / 64, 128>>>(fA, fB, coors, w_sub2, n);
    conv_fine_tiled<64, 64, 8><<<(n + 63) / 64, 128>>>(fB, fA, coors, w_sub3, n);

    // coarse level (dense)
    conv_grid_tiled<64, 64, 8, FS, 27, 1><<<NC1 / 64, 128>>>(fA, cA, w_down0, nullptr);
    conv_grid_tiled<64, 96, 8, CS, 27, 0><<<NC1 / 64, 192>>>(cA, cB, w_sub4, maskp);
    conv_grid_tiled<96, 96, 8, CS, 27, 0><<<NC1 / 64, 192>>>(cB, cA, w_sub5, maskp);
    conv_grid_tiled<96, 96, 8, CS, 8, 2><<<NC2 / 64, 192>>>(cA, c2p, w_down1, nullptr);

    // decoder
    inv1_kernel<<<NC1, 64>>>(c2p, cB, pwi1, maskp);
    inv0_kernel<<<n, 32>>>(cB, (float*)d_out, coors, pwi0, n);
}